// round 12
// baseline (speedup 1.0000x reference)
#include <cuda_runtime.h>
#include <cuda_bf16.h>
#include <math.h>
#include <stdint.h>

#define Bdim 2
#define Hlat 128
#define Wlon 256
#define Cdim 256
#define HWsz (Hlat*Wlon)
#define MAXCOL 1536

// Scratch (allocation-free rule: __device__ globals)
__device__ float g_q[(size_t)Bdim*HWsz*Cdim];   // (b,h,w,c), pre-scaled by 1/16
__device__ float g_k[(size_t)Bdim*HWsz*Cdim];
__device__ float g_v[(size_t)Bdim*HWsz*Cdim];
__device__ int   g_cnt[Hlat*Hlat];
__device__ int   g_arc[Hlat*Hlat];

// ---------------------------------------------------------------------------
// Tensor-core helpers (sm_80-baseline PTX)
// ---------------------------------------------------------------------------
__device__ __forceinline__ uint32_t smem_u32(const void* p) {
    uint32_t a;
    asm("{ .reg .u64 t; cvta.to.shared.u64 t, %1; cvt.u32.u64 %0, t; }" : "=r"(a) : "l"(p));
    return a;
}
__device__ __forceinline__ void ldsm_x4(uint32_t* r, uint32_t addr) {
    asm volatile("ldmatrix.sync.aligned.m8n8.x4.shared.b16 {%0,%1,%2,%3}, [%4];"
        : "=r"(r[0]), "=r"(r[1]), "=r"(r[2]), "=r"(r[3]) : "r"(addr));
}
__device__ __forceinline__ void ldsm_x4t(uint32_t* r, uint32_t addr) {
    asm volatile("ldmatrix.sync.aligned.m8n8.x4.trans.shared.b16 {%0,%1,%2,%3}, [%4];"
        : "=r"(r[0]), "=r"(r[1]), "=r"(r[2]), "=r"(r[3]) : "r"(addr));
}
__device__ __forceinline__ void mma_bf(float* d, const uint32_t* a, uint32_t b0, uint32_t b1) {
    asm volatile(
        "mma.sync.aligned.m16n8k16.row.col.f32.bf16.bf16.f32 "
        "{%0,%1,%2,%3}, {%4,%5,%6,%7}, {%8,%9}, {%0,%1,%2,%3};"
        : "+f"(d[0]), "+f"(d[1]), "+f"(d[2]), "+f"(d[3])
        : "r"(a[0]), "r"(a[1]), "r"(a[2]), "r"(a[3]), "r"(b0), "r"(b1));
}
__device__ __forceinline__ uint32_t packbf(float lo, float hi) {
    uint32_t r;
    asm("cvt.rn.bf16x2.f32 %0, %1, %2;" : "=r"(r) : "f"(hi), "f"(lo));
    return r;
}
__device__ __forceinline__ float bflo_f(uint32_t h) { return __uint_as_float(h << 16); }
__device__ __forceinline__ float bfhi_f(uint32_t h) { return __uint_as_float(h & 0xffff0000u); }

// ---------------------------------------------------------------------------
// Arc table precompute
// ---------------------------------------------------------------------------
__global__ void zero_cnt_kernel() { g_cnt[blockIdx.x * 256 + threadIdx.x] = 0; }
__global__ void count_kernel(const int* __restrict__ rows, const int* __restrict__ cols, int nnz) {
    int i = blockIdx.x * 256 + threadIdx.x;
    if (i >= nnz) return;
    atomicAdd(&g_cnt[rows[i] * Hlat + (cols[i] >> 8)], 1);
}
__global__ void arc_kernel() {
    int i = blockIdx.x * 256 + threadIdx.x;
    int c = g_cnt[i];
    g_arc[i] = (c == 0) ? -1 : ((c >= 256) ? 128 : ((c - 1) >> 1));
}

// ---------------------------------------------------------------------------
// QKV projection via mma.sync bf16 hi/lo (3-term). Round-9 config (252 us).
// ---------------------------------------------------------------------------
__global__ __launch_bounds__(256, 2) void qkv_mma_kernel(
    const float* __restrict__ x,
    const float* __restrict__ wq, const float* __restrict__ wk, const float* __restrict__ wv,
    const float* __restrict__ bq, const float* __restrict__ bk, const float* __restrict__ bv)
{
    __shared__ __align__(16) unsigned short A_hi[32][136];
    __shared__ __align__(16) unsigned short A_lo[32][136];
    __shared__ __align__(16) unsigned short W_hi[64][40];
    __shared__ __align__(16) unsigned short W_lo[64][40];

    int tid = threadIdx.x, lane = tid & 31, warp = tid >> 5;
    int p0 = blockIdx.x * 128;
    int nb = blockIdx.y;
    int b  = blockIdx.z;
    int mat = nb >> 2;
    int j0 = (nb & 3) * 64;

    const float* Wm   = (mat == 0) ? wq : (mat == 1) ? wk : wv;
    const float* Bias = (mat == 0) ? bq : (mat == 1) ? bk : bv;
    float*       Out  = (mat == 0) ? g_q : (mat == 1) ? g_k : g_v;
    float osc = (mat == 0) ? 0.0625f : 1.0f;

    const float* xb = x + (size_t)b * Cdim * HWsz;

    uint32_t a_hi_base = smem_u32(A_hi);
    uint32_t a_lo_base = smem_u32(A_lo);
    uint32_t w_hi_base = smem_u32(W_hi);
    uint32_t w_lo_base = smem_u32(W_lo);

    float acc[2][4][4];
    #pragma unroll
    for (int i = 0; i < 2; ++i)
        #pragma unroll
        for (int j = 0; j < 4; ++j)
            #pragma unroll
            for (int k = 0; k < 4; ++k) acc[i][j][k] = 0.f;

    int wp = warp & 3, wj = warp >> 2;
    int g  = lane >> 3, jl = lane & 7;
    int a_krow = jl + ((g & 2) ? 8 : 0);
    int a_mcol = (g & 1) ? 8 : 0;
    int b_nrow = jl + ((g & 2) ? 8 : 0);
    int b_kcol = (g & 1) ? 8 : 0;

    for (int chunk = 0; chunk < 8; ++chunk) {
        int c0 = chunk * 32;
        #pragma unroll
        for (int it = 0; it < 4; ++it) {
            int idx = tid + it * 256;
            int r = idx >> 5, c4 = idx & 31;
            float4 v = *(const float4*)(xb + (size_t)(c0 + r) * HWsz + p0 + c4 * 4);
            uint32_t h0 = packbf(v.x, v.y), h1 = packbf(v.z, v.w);
            float lx = v.x - bflo_f(h0), ly = v.y - bfhi_f(h0);
            float lz = v.z - bflo_f(h1), lw = v.w - bfhi_f(h1);
            *(uint2*)&A_hi[r][c4 * 4] = make_uint2(h0, h1);
            *(uint2*)&A_lo[r][c4 * 4] = make_uint2(packbf(lx, ly), packbf(lz, lw));
        }
        #pragma unroll
        for (int it = 0; it < 2; ++it) {
            int idx = tid + it * 256;
            int j = idx >> 3, f4 = idx & 7;
            float4 v = *(const float4*)(Wm + (size_t)(j0 + j) * Cdim + c0 + f4 * 4);
            uint32_t h0 = packbf(v.x, v.y), h1 = packbf(v.z, v.w);
            float lx = v.x - bflo_f(h0), ly = v.y - bfhi_f(h0);
            float lz = v.z - bflo_f(h1), lw = v.w - bfhi_f(h1);
            *(uint2*)&W_hi[j][f4 * 4] = make_uint2(h0, h1);
            *(uint2*)&W_lo[j][f4 * 4] = make_uint2(packbf(lx, ly), packbf(lz, lw));
        }
        __syncthreads();

        #pragma unroll
        for (int ks = 0; ks < 2; ++ks) {
            int k0 = ks * 16;
            uint32_t ah[2][4], al[2][4];
            #pragma unroll
            for (int mt = 0; mt < 2; ++mt) {
                int m0 = wp * 32 + mt * 16;
                uint32_t off = (uint32_t)((k0 + a_krow) * 272 + (m0 + a_mcol) * 2);
                ldsm_x4t(ah[mt], a_hi_base + off);
                ldsm_x4t(al[mt], a_lo_base + off);
            }
            #pragma unroll
            for (int np = 0; np < 2; ++np) {
                int n0 = wj * 32 + np * 16;
                uint32_t off = (uint32_t)((n0 + b_nrow) * 80 + (k0 + b_kcol) * 2);
                uint32_t bh[4], bl[4];
                ldsm_x4(bh, w_hi_base + off);
                ldsm_x4(bl, w_lo_base + off);
                #pragma unroll
                for (int mt = 0; mt < 2; ++mt) {
                    mma_bf(acc[mt][np * 2],     ah[mt], bh[0], bh[1]);
                    mma_bf(acc[mt][np * 2],     al[mt], bh[0], bh[1]);
                    mma_bf(acc[mt][np * 2],     ah[mt], bl[0], bl[1]);
                    mma_bf(acc[mt][np * 2 + 1], ah[mt], bh[2], bh[3]);
                    mma_bf(acc[mt][np * 2 + 1], al[mt], bh[2], bh[3]);
                    mma_bf(acc[mt][np * 2 + 1], ah[mt], bl[2], bl[3]);
                }
            }
        }
        __syncthreads();
    }

    float* opb = Out + (size_t)b * HWsz * Cdim;
    int r0 = lane >> 2, cp = (lane & 3) * 2;
    #pragma unroll
    for (int mt = 0; mt < 2; ++mt) {
        int p = p0 + wp * 32 + mt * 16 + r0;
        #pragma unroll
        for (int nt = 0; nt < 4; ++nt) {
            int jc = j0 + wj * 32 + nt * 8 + cp;
            float b0v = Bias[jc], b1v = Bias[jc + 1];
            float2 s0, s1;
            s0.x = fmaf(acc[mt][nt][0], osc, b0v);
            s0.y = fmaf(acc[mt][nt][1], osc, b1v);
            s1.x = fmaf(acc[mt][nt][2], osc, b0v);
            s1.y = fmaf(acc[mt][nt][3], osc, b1v);
            *(float2*)(opb + (size_t)p * Cdim + jc) = s0;
            *(float2*)(opb + (size_t)(p + 8) * Cdim + jc) = s1;
        }
    }
}

// ---------------------------------------------------------------------------
// Single-pass attention, T=4. No softmax max (logits bounded ~|6|; max shift
// cancels exactly in num/denom). Warp owns a column end-to-end; zero syncs in
// the main loop. FIX vs round 11: lanes sharing tq hold identical alpha, so
// the per-lane d is already the warp denominator — no cross-lane sum.
// ---------------------------------------------------------------------------
#define DOFF_Q     0          // float[4][256]   4096
#define DOFF_OFF   4096       // int[MAXCOL]     6144
#define DOFF_AUX   10240      // int[MAXCOL]     6144
#define DOFF_QW    16384      // float[128]      512
#define DOFF_ARC   16896      // int[128]        512
#define DOFF_WID   17408      // int[128]        512
#define DOFF_START 17920      // int[129]        520 (padded)
#define DOFF_DRED  18440      // float[32]       128
#define DOFF_INV   18568      // float[4]        120 pad
#define DOFF_SP    18688      // float[8][4][256] 32768
#define ATTN_SMEM  51456

__global__ __launch_bounds__(256, 2) void attn_kernel(
    const float* __restrict__ qw_lat, float* __restrict__ out)
{
    extern __shared__ char dsm[];
    float* s_q     = (float*)(dsm + DOFF_Q);
    int*   s_off   = (int*)(dsm + DOFF_OFF);
    int*   s_aux   = (int*)(dsm + DOFF_AUX);
    float* s_qw    = (float*)(dsm + DOFF_QW);
    int*   s_arcv  = (int*)(dsm + DOFF_ARC);
    int*   s_widv  = (int*)(dsm + DOFF_WID);
    int*   s_start = (int*)(dsm + DOFF_START);
    float* s_dred  = (float*)(dsm + DOFF_DRED);
    float* s_inv   = (float*)(dsm + DOFF_INV);
    float* sp      = (float*)(dsm + DOFF_SP);

    int wo0 = blockIdx.x * 4;
    int ho = blockIdx.y, b = blockIdx.z;
    int tid = threadIdx.x, lane = tid & 31, warp = tid >> 5;

    if (tid < Hlat) {
        int a = g_arc[ho * Hlat + tid];
        s_arcv[tid] = a;
        int w = (a < 0) ? 0 : (2 * a + 4);
        s_widv[tid] = (w > 256) ? 256 : w;
        s_qw[tid] = qw_lat[tid];
    }
    {
        int t = tid >> 6; int c4 = (tid & 63) * 4;
        *(float4*)&s_q[t * 256 + c4] =
            *(const float4*)(g_q + (((size_t)b * Hlat + ho) * Wlon + wo0 + t) * Cdim + c4);
    }
    __syncthreads();

    if (warp == 0) {
        int b0 = lane * 4;
        int w0 = s_widv[b0], w1 = s_widv[b0+1], w2 = s_widv[b0+2], w3 = s_widv[b0+3];
        int p1 = w0 + w1, p2 = p1 + w2, tot = p2 + w3;
        int inc = tot;
        #pragma unroll
        for (int o = 1; o < 32; o <<= 1) {
            int nv = __shfl_up_sync(0xffffffffu, inc, o);
            if (lane >= o) inc += nv;
        }
        int base = inc - tot;
        s_start[b0] = base; s_start[b0+1] = base + w0;
        s_start[b0+2] = base + p1; s_start[b0+3] = base + p2;
        if (lane == 31) s_start[Hlat] = inc;
    }
    __syncthreads();
    int ncol = s_start[Hlat];
    if (ncol > MAXCOL) ncol = MAXCOL;

    for (int j = tid; j < ncol; j += 256) {
        int lo = 0, hi2 = Hlat;
        while (lo + 1 < hi2) {
            int mid = (lo + hi2) >> 1;
            if (s_start[mid] <= j) lo = mid; else hi2 = mid;
        }
        int a = s_arcv[lo];
        int w = wo0 - a + (j - s_start[lo]);
        s_off[j] = lo * 256 + (w & 255);
        s_aux[j] = (a << 8) | ((w - wo0) & 255);
    }
    __syncthreads();

    // Q fragments (4 t x 8 floats per lane)
    float4 qa[4], qb[4];
    #pragma unroll
    for (int t = 0; t < 4; ++t) {
        qa[t] = *(const float4*)&s_q[t * 256 + lane * 4];
        qb[t] = *(const float4*)&s_q[t * 256 + 128 + lane * 4];
    }
    const float* kb = g_k + (size_t)b * HWsz * Cdim;
    const float* vb = g_v + (size_t)b * HWsz * Cdim;
    bool b1 = (lane & 1), b2 = (lane & 2);
    const int tq = lane & 3;

    // O partial accumulators: slot s holds t = tq^s, channels lane*4.. & 128+lane*4..
    float acc[4][8];
    #pragma unroll
    for (int s = 0; s < 4; ++s)
        #pragma unroll
        for (int c = 0; c < 8; ++c) acc[s][c] = 0.f;
    float d = 0.f;

    for (int j = warp; j < ncol; j += 8) {
        int off = s_off[j];
        int aux = s_aux[j];
        const float* kr = kb + (size_t)off * Cdim;
        const float* vr = vb + (size_t)off * Cdim;
        float4 k0 = *(const float4*)(kr + lane * 4);
        float4 k1 = *(const float4*)(kr + 128 + lane * 4);
        float4 v0 = *(const float4*)(vr + lane * 4);
        float4 v1 = *(const float4*)(vr + 128 + lane * 4);
        float p[4];
        #pragma unroll
        for (int t = 0; t < 4; ++t) {
            float s = k0.x * qa[t].x;
            s = fmaf(k0.y, qa[t].y, s); s = fmaf(k0.z, qa[t].z, s); s = fmaf(k0.w, qa[t].w, s);
            s = fmaf(k1.x, qb[t].x, s); s = fmaf(k1.y, qb[t].y, s);
            s = fmaf(k1.z, qb[t].z, s); s = fmaf(k1.w, qb[t].w, s);
            p[t] = s;
        }
        // transpose-reduce: every lane ends with the full sum for t = lane&3
        float uA = b1 ? p[1] : p[0], wA = b1 ? p[0] : p[1];
        uA += __shfl_xor_sync(0xffffffffu, wA, 1);
        float uB = b1 ? p[3] : p[2], wB = b1 ? p[2] : p[3];
        uB += __shfl_xor_sync(0xffffffffu, wB, 1);
        float v = b2 ? uB : uA, xx = b2 ? uA : uB;
        v += __shfl_xor_sync(0xffffffffu, xx, 2);
        v += __shfl_xor_sync(0xffffffffu, v, 4);
        v += __shfl_xor_sync(0xffffffffu, v, 8);
        v += __shfl_xor_sync(0xffffffffu, v, 16);
        // mask + exp for own t
        int a = aux >> 8;
        int dw = ((aux & 255) - tq) & 255;
        bool valid = (dw <= a) || (dw >= 256 - a);
        float alpha = valid ? __expf(v) * s_qw[off >> 8] : 0.f;
        d += alpha;     // NOTE: all lanes with same tq hold identical alpha;
                        // d is already the full warp denominator for t = tq.
        // broadcast: a1 = alpha(t=tq^1), a2 = (t=tq^2), a3 = (t=tq^3)
        float a1 = __shfl_xor_sync(0xffffffffu, alpha, 1);
        float a2 = __shfl_xor_sync(0xffffffffu, alpha, 2);
        float a3 = __shfl_xor_sync(0xffffffffu, a1, 2);
        acc[0][0] = fmaf(alpha, v0.x, acc[0][0]); acc[0][1] = fmaf(alpha, v0.y, acc[0][1]);
        acc[0][2] = fmaf(alpha, v0.z, acc[0][2]); acc[0][3] = fmaf(alpha, v0.w, acc[0][3]);
        acc[0][4] = fmaf(alpha, v1.x, acc[0][4]); acc[0][5] = fmaf(alpha, v1.y, acc[0][5]);
        acc[0][6] = fmaf(alpha, v1.z, acc[0][6]); acc[0][7] = fmaf(alpha, v1.w, acc[0][7]);
        acc[1][0] = fmaf(a1, v0.x, acc[1][0]); acc[1][1] = fmaf(a1, v0.y, acc[1][1]);
        acc[1][2] = fmaf(a1, v0.z, acc[1][2]); acc[1][3] = fmaf(a1, v0.w, acc[1][3]);
        acc[1][4] = fmaf(a1, v1.x, acc[1][4]); acc[1][5] = fmaf(a1, v1.y, acc[1][5]);
        acc[1][6] = fmaf(a1, v1.z, acc[1][6]); acc[1][7] = fmaf(a1, v1.w, acc[1][7]);
        acc[2][0] = fmaf(a2, v0.x, acc[2][0]); acc[2][1] = fmaf(a2, v0.y, acc[2][1]);
        acc[2][2] = fmaf(a2, v0.z, acc[2][2]); acc[2][3] = fmaf(a2, v0.w, acc[2][3]);
        acc[2][4] = fmaf(a2, v1.x, acc[2][4]); acc[2][5] = fmaf(a2, v1.y, acc[2][5]);
        acc[2][6] = fmaf(a2, v1.z, acc[2][6]); acc[2][7] = fmaf(a2, v1.w, acc[2][7]);
        acc[3][0] = fmaf(a3, v0.x, acc[3][0]); acc[3][1] = fmaf(a3, v0.y, acc[3][1]);
        acc[3][2] = fmaf(a3, v0.z, acc[3][2]); acc[3][3] = fmaf(a3, v0.w, acc[3][3]);
        acc[3][4] = fmaf(a3, v1.x, acc[3][4]); acc[3][5] = fmaf(a3, v1.y, acc[3][5]);
        acc[3][6] = fmaf(a3, v1.z, acc[3][6]); acc[3][7] = fmaf(a3, v1.w, acc[3][7]);
    }

    // denominator per (warp, t): lanes 0..3 already hold the correct value
    if (lane < 4) s_dred[warp * 4 + lane] = d;

    // O partials -> smem [warp][t][256]
    #pragma unroll
    for (int s = 0; s < 4; ++s) {
        int t = tq ^ s;
        float* dst = sp + (warp * 4 + t) * 256;
        *(float4*)(dst + lane * 4) = make_float4(acc[s][0], acc[s][1], acc[s][2], acc[s][3]);
        *(float4*)(dst + 128 + lane * 4) = make_float4(acc[s][4], acc[s][5], acc[s][6], acc[s][7]);
    }
    __syncthreads();
    if (tid < 4) {
        float dd = 0.f;
        #pragma unroll
        for (int w = 0; w < 8; ++w) dd += s_dred[w * 4 + tid];
        s_inv[tid] = 1.0f / dd;
    }
    __syncthreads();

    float o[4];
    #pragma unroll
    for (int t = 0; t < 4; ++t) {
        float s = 0.f;
        #pragma unroll
        for (int w = 0; w < 8; ++w) s += sp[(w * 4 + t) * 256 + tid];
        o[t] = s * s_inv[t];
    }
    *(float4*)(out + (((size_t)b * Cdim + tid) * Hlat + ho) * Wlon + wo0) =
        make_float4(o[0], o[1], o[2], o[3]);
}

// ---------------------------------------------------------------------------
extern "C" void kernel_launch(void* const* d_in, const int* in_sizes, int n_in,
                              void* d_out, int out_size) {
    const float* query = (const float*)d_in[0];
    const float* wq    = (const float*)d_in[1];
    const float* wk    = (const float*)d_in[2];
    const float* wv    = (const float*)d_in[3];
    const float* bq    = (const float*)d_in[4];
    const float* bk    = (const float*)d_in[5];
    const float* bv    = (const float*)d_in[6];
    const float* qw    = (const float*)d_in[7];
    const int*   rows  = (const int*)d_in[8];
    const int*   cols  = (const int*)d_in[9];
    int nnz = in_sizes[8];
    float* out = (float*)d_out;

    cudaFuncSetAttribute(attn_kernel,
                         cudaFuncAttributeMaxDynamicSharedMemorySize, ATTN_SMEM);

    zero_cnt_kernel<<<Hlat * Hlat / 256, 256>>>();
    count_kernel<<<(nnz + 255) / 256, 256>>>(rows, cols, nnz);
    arc_kernel<<<Hlat * Hlat / 256, 256>>>();
    qkv_mma_kernel<<<dim3(HWsz / 128, 12, Bdim), 256>>>(query, wq, wk, wv, bq, bk, bv);
    attn_kernel<<<dim3(Wlon / 4, Hlat, Bdim), 256, ATTN_SMEM>>>(qw, out);
}

// round 13
// speedup vs baseline: 1.1325x; 1.1325x over previous
#include <cuda_runtime.h>
#include <cuda_bf16.h>
#include <math.h>
#include <stdint.h>

#define Bdim 2
#define Hlat 128
#define Wlon 256
#define Cdim 256
#define HWsz (Hlat*Wlon)
#define MAXCOL 1536

// Scratch (allocation-free rule: __device__ globals)
__device__ float g_q[(size_t)Bdim*HWsz*Cdim];   // (b,h,w,c), pre-scaled by 1/16
__device__ float g_k[(size_t)Bdim*HWsz*Cdim];
__device__ float g_v[(size_t)Bdim*HWsz*Cdim];
__device__ int   g_cnt[Hlat*Hlat];
__device__ int   g_arc[Hlat*Hlat];

// ---------------------------------------------------------------------------
// Helpers (sm_80-baseline PTX)
// ---------------------------------------------------------------------------
__device__ __forceinline__ uint32_t smem_u32(const void* p) {
    uint32_t a;
    asm("{ .reg .u64 t; cvta.to.shared.u64 t, %1; cvt.u32.u64 %0, t; }" : "=r"(a) : "l"(p));
    return a;
}
__device__ __forceinline__ void ldsm_x4(uint32_t* r, uint32_t addr) {
    asm volatile("ldmatrix.sync.aligned.m8n8.x4.shared.b16 {%0,%1,%2,%3}, [%4];"
        : "=r"(r[0]), "=r"(r[1]), "=r"(r[2]), "=r"(r[3]) : "r"(addr));
}
__device__ __forceinline__ void ldsm_x4t(uint32_t* r, uint32_t addr) {
    asm volatile("ldmatrix.sync.aligned.m8n8.x4.trans.shared.b16 {%0,%1,%2,%3}, [%4];"
        : "=r"(r[0]), "=r"(r[1]), "=r"(r[2]), "=r"(r[3]) : "r"(addr));
}
__device__ __forceinline__ void mma_bf(float* d, const uint32_t* a, uint32_t b0, uint32_t b1) {
    asm volatile(
        "mma.sync.aligned.m16n8k16.row.col.f32.bf16.bf16.f32 "
        "{%0,%1,%2,%3}, {%4,%5,%6,%7}, {%8,%9}, {%0,%1,%2,%3};"
        : "+f"(d[0]), "+f"(d[1]), "+f"(d[2]), "+f"(d[3])
        : "r"(a[0]), "r"(a[1]), "r"(a[2]), "r"(a[3]), "r"(b0), "r"(b1));
}
__device__ __forceinline__ uint32_t packbf(float lo, float hi) {
    uint32_t r;
    asm("cvt.rn.bf16x2.f32 %0, %1, %2;" : "=r"(r) : "f"(hi), "f"(lo));
    return r;
}
__device__ __forceinline__ float bflo_f(uint32_t h) { return __uint_as_float(h << 16); }
__device__ __forceinline__ float bfhi_f(uint32_t h) { return __uint_as_float(h & 0xffff0000u); }
__device__ __forceinline__ void cp_async16(uint32_t dst, const void* src) {
    asm volatile("cp.async.cg.shared.global [%0], [%1], 16;" :: "r"(dst), "l"(src));
}
__device__ __forceinline__ void cp_commit() {
    asm volatile("cp.async.commit_group;" ::: "memory");
}
__device__ __forceinline__ void cp_wait1() {
    asm volatile("cp.async.wait_group 1;" ::: "memory");
}
__device__ __forceinline__ void cp_wait0() {
    asm volatile("cp.async.wait_group 0;" ::: "memory");
}

// ---------------------------------------------------------------------------
// Arc table precompute
// ---------------------------------------------------------------------------
__global__ void zero_cnt_kernel() { g_cnt[blockIdx.x * 256 + threadIdx.x] = 0; }
__global__ void count_kernel(const int* __restrict__ rows, const int* __restrict__ cols, int nnz) {
    int i = blockIdx.x * 256 + threadIdx.x;
    if (i >= nnz) return;
    atomicAdd(&g_cnt[rows[i] * Hlat + (cols[i] >> 8)], 1);
}
__global__ void arc_kernel() {
    int i = blockIdx.x * 256 + threadIdx.x;
    int c = g_cnt[i];
    g_arc[i] = (c == 0) ? -1 : ((c >= 256) ? 128 : ((c - 1) >> 1));
}

// ---------------------------------------------------------------------------
// QKV projection: mma.sync bf16 hi/lo (3-term) + cp.async double-buffered
// staging. Block = 128p x 64j of one matrix; warp tile 32p x 32j.
// Dynamic smem layout (bytes):
// ---------------------------------------------------------------------------
#define GOFF_XRAW 0            // float[2][32][128]  32768
#define GOFF_WRAW 32768        // float[2][64][32]   16384
#define GOFF_AHI  49152        // ushort[32][136]     8704
#define GOFF_ALO  57856        // ushort[32][136]     8704
#define GOFF_WHI  66560        // ushort[64][40]      5120
#define GOFF_WLO  71680        // ushort[64][40]      5120
#define GEMM_SMEM 76800

__global__ __launch_bounds__(256, 2) void qkv_mma_kernel(
    const float* __restrict__ x,
    const float* __restrict__ wq, const float* __restrict__ wk, const float* __restrict__ wv,
    const float* __restrict__ bq, const float* __restrict__ bk, const float* __restrict__ bv)
{
    extern __shared__ char dsm[];
    uint32_t sb = smem_u32(dsm);

    int tid = threadIdx.x, lane = tid & 31, warp = tid >> 5;
    int p0 = blockIdx.x * 128;
    int nb = blockIdx.y;
    int b  = blockIdx.z;
    int mat = nb >> 2;
    int j0 = (nb & 3) * 64;

    const float* Wm   = (mat == 0) ? wq : (mat == 1) ? wk : wv;
    const float* Bias = (mat == 0) ? bq : (mat == 1) ? bk : bv;
    float*       Out  = (mat == 0) ? g_q : (mat == 1) ? g_k : g_v;
    float osc = (mat == 0) ? 0.0625f : 1.0f;

    const float* xb = x + (size_t)b * Cdim * HWsz;

    uint32_t a_hi_base = sb + GOFF_AHI;
    uint32_t a_lo_base = sb + GOFF_ALO;
    uint32_t w_hi_base = sb + GOFF_WHI;
    uint32_t w_lo_base = sb + GOFF_WLO;

    float acc[2][4][4];
    #pragma unroll
    for (int i = 0; i < 2; ++i)
        #pragma unroll
        for (int j = 0; j < 4; ++j)
            #pragma unroll
            for (int k = 0; k < 4; ++k) acc[i][j][k] = 0.f;

    int wp = warp & 3, wj = warp >> 2;
    int g  = lane >> 3, jl = lane & 7;
    int a_krow = jl + ((g & 2) ? 8 : 0);
    int a_mcol = (g & 1) ? 8 : 0;
    int b_nrow = jl + ((g & 2) ? 8 : 0);
    int b_kcol = (g & 1) ? 8 : 0;

    // prefetch lambda: raw f32 chunk -> staging ring
    auto prefetch = [&](int chunk, int buf) {
        int c0 = chunk * 32;
        #pragma unroll
        for (int it = 0; it < 4; ++it) {
            int idx = tid + it * 256;
            int r = idx >> 5, c4 = idx & 31;
            cp_async16(sb + GOFF_XRAW + buf * 16384 + r * 512 + c4 * 16,
                       xb + (size_t)(c0 + r) * HWsz + p0 + c4 * 4);
        }
        #pragma unroll
        for (int it = 0; it < 2; ++it) {
            int idx = tid + it * 256;
            int j = idx >> 3, f4 = idx & 7;
            cp_async16(sb + GOFF_WRAW + buf * 8192 + j * 128 + f4 * 16,
                       Wm + (size_t)(j0 + j) * Cdim + c0 + f4 * 4);
        }
    };

    prefetch(0, 0);
    cp_commit();

    for (int chunk = 0; chunk < 8; ++chunk) {
        int buf = chunk & 1;
        if (chunk < 7) {
            prefetch(chunk + 1, buf ^ 1);
            cp_commit();
            cp_wait1();
        } else {
            cp_wait0();
        }
        __syncthreads();   // staged raw data visible; prior mma done with hi/lo

        // convert raw f32 -> bf16 hi/lo tiles
        {
            const float* xr = (const float*)(dsm + GOFF_XRAW + buf * 16384);
            #pragma unroll
            for (int it = 0; it < 4; ++it) {
                int idx = tid + it * 256;
                int r = idx >> 5, c4 = idx & 31;
                float4 v = *(const float4*)(xr + r * 128 + c4 * 4);
                uint32_t h0 = packbf(v.x, v.y), h1 = packbf(v.z, v.w);
                float lx = v.x - bflo_f(h0), ly = v.y - bfhi_f(h0);
                float lz = v.z - bflo_f(h1), lw = v.w - bfhi_f(h1);
                *(uint2*)(dsm + GOFF_AHI + (r * 136 + c4 * 4) * 2) = make_uint2(h0, h1);
                *(uint2*)(dsm + GOFF_ALO + (r * 136 + c4 * 4) * 2) =
                    make_uint2(packbf(lx, ly), packbf(lz, lw));
            }
            const float* wr = (const float*)(dsm + GOFF_WRAW + buf * 8192);
            #pragma unroll
            for (int it = 0; it < 2; ++it) {
                int idx = tid + it * 256;
                int j = idx >> 3, f4 = idx & 7;
                float4 v = *(const float4*)(wr + j * 32 + f4 * 4);
                uint32_t h0 = packbf(v.x, v.y), h1 = packbf(v.z, v.w);
                float lx = v.x - bflo_f(h0), ly = v.y - bfhi_f(h0);
                float lz = v.z - bflo_f(h1), lw = v.w - bfhi_f(h1);
                *(uint2*)(dsm + GOFF_WHI + (j * 40 + f4 * 4) * 2) = make_uint2(h0, h1);
                *(uint2*)(dsm + GOFF_WLO + (j * 40 + f4 * 4) * 2) =
                    make_uint2(packbf(lx, ly), packbf(lz, lw));
            }
        }
        __syncthreads();

        #pragma unroll
        for (int ks = 0; ks < 2; ++ks) {
            int k0 = ks * 16;
            uint32_t ah[2][4], al[2][4];
            #pragma unroll
            for (int mt = 0; mt < 2; ++mt) {
                int m0 = wp * 32 + mt * 16;
                uint32_t off = (uint32_t)((k0 + a_krow) * 272 + (m0 + a_mcol) * 2);
                ldsm_x4t(ah[mt], a_hi_base + off);
                ldsm_x4t(al[mt], a_lo_base + off);
            }
            #pragma unroll
            for (int np = 0; np < 2; ++np) {
                int n0 = wj * 32 + np * 16;
                uint32_t off = (uint32_t)((n0 + b_nrow) * 80 + (k0 + b_kcol) * 2);
                uint32_t bh[4], bl[4];
                ldsm_x4(bh, w_hi_base + off);
                ldsm_x4(bl, w_lo_base + off);
                #pragma unroll
                for (int mt = 0; mt < 2; ++mt) {
                    mma_bf(acc[mt][np * 2],     ah[mt], bh[0], bh[1]);
                    mma_bf(acc[mt][np * 2],     al[mt], bh[0], bh[1]);
                    mma_bf(acc[mt][np * 2],     ah[mt], bl[0], bl[1]);
                    mma_bf(acc[mt][np * 2 + 1], ah[mt], bh[2], bh[3]);
                    mma_bf(acc[mt][np * 2 + 1], al[mt], bh[2], bh[3]);
                    mma_bf(acc[mt][np * 2 + 1], ah[mt], bl[2], bl[3]);
                }
            }
        }
    }

    float* opb = Out + (size_t)b * HWsz * Cdim;
    int r0 = lane >> 2, cp = (lane & 3) * 2;
    #pragma unroll
    for (int mt = 0; mt < 2; ++mt) {
        int p = p0 + wp * 32 + mt * 16 + r0;
        #pragma unroll
        for (int nt = 0; nt < 4; ++nt) {
            int jc = j0 + wj * 32 + nt * 8 + cp;
            float b0v = Bias[jc], b1v = Bias[jc + 1];
            float2 s0, s1;
            s0.x = fmaf(acc[mt][nt][0], osc, b0v);
            s0.y = fmaf(acc[mt][nt][1], osc, b1v);
            s1.x = fmaf(acc[mt][nt][2], osc, b0v);
            s1.y = fmaf(acc[mt][nt][3], osc, b1v);
            *(float2*)(opb + (size_t)p * Cdim + jc) = s0;
            *(float2*)(opb + (size_t)(p + 8) * Cdim + jc) = s1;
        }
    }
}

// ---------------------------------------------------------------------------
// Attention over distinct columns, T=4 (round-4/10 measured config, ~815 us).
// ---------------------------------------------------------------------------
__global__ __launch_bounds__(256) void attn_kernel(
    const float* __restrict__ qw_lat,
    float* __restrict__ out)
{
    __shared__ __align__(16) float s_q[4][Cdim];
    __shared__ __align__(16) float s_alpha[MAXCOL * 4];
    __shared__ __align__(16) int   s_off[MAXCOL];
    __shared__ __align__(16) int   s_aux[MAXCOL];
    __shared__ int   s_arcv[Hlat];
    __shared__ int   s_wid[Hlat];
    __shared__ int   s_start[Hlat + 1];
    __shared__ float s_red[32];
    __shared__ float s_m[4];
    __shared__ float s_inv[4];

    int wo0 = blockIdx.x * 4;
    int ho = blockIdx.y, b = blockIdx.z;
    int tid = threadIdx.x, lane = tid & 31, warp = tid >> 5;

    if (tid < Hlat) {
        int a = g_arc[ho * Hlat + tid];
        s_arcv[tid] = a;
        int w = (a < 0) ? 0 : (2 * a + 4);
        s_wid[tid] = (w > 256) ? 256 : w;
    }
    {
        int t = tid >> 6; int c4 = (tid & 63) * 4;
        *(float4*)&s_q[t][c4] =
            *(const float4*)(g_q + (((size_t)b * Hlat + ho) * Wlon + wo0 + t) * Cdim + c4);
    }
    __syncthreads();

    if (warp == 0) {
        int b0 = lane * 4;
        int w0 = s_wid[b0], w1 = s_wid[b0 + 1], w2 = s_wid[b0 + 2], w3 = s_wid[b0 + 3];
        int p1 = w0 + w1, p2 = p1 + w2, tot = p2 + w3;
        int inc = tot;
        #pragma unroll
        for (int o = 1; o < 32; o <<= 1) {
            int nv = __shfl_up_sync(0xffffffffu, inc, o);
            if (lane >= o) inc += nv;
        }
        int base = inc - tot;
        s_start[b0] = base; s_start[b0 + 1] = base + w0;
        s_start[b0 + 2] = base + p1; s_start[b0 + 3] = base + p2;
        if (lane == 31) s_start[Hlat] = inc;
    }
    __syncthreads();
    int ncol = s_start[Hlat];
    if (ncol > MAXCOL) ncol = MAXCOL;

    for (int j = tid; j < ncol; j += 256) {
        int lo = 0, hi2 = Hlat;
        while (lo + 1 < hi2) {
            int mid = (lo + hi2) >> 1;
            if (s_start[mid] <= j) lo = mid; else hi2 = mid;
        }
        int a = s_arcv[lo];
        int w = wo0 - a + (j - s_start[lo]);
        s_off[j] = lo * 256 + (w & 255);
        s_aux[j] = (a << 8) | ((w - wo0) & 255);
    }
    __syncthreads();

    const int tq = lane & 3;
    float4 qa[4], qb[4];
    #pragma unroll
    for (int t = 0; t < 4; ++t) {
        qa[t] = *(const float4*)&s_q[t][lane * 4];
        qb[t] = *(const float4*)&s_q[t][128 + lane * 4];
    }
    const float* kb = g_k + (size_t)b * HWsz * Cdim;
    bool b1 = (lane & 1), b2 = (lane & 2);
    float lmax = -INFINITY;

    #pragma unroll 2
    for (int j = warp; j < ncol; j += 8) {
        const float* kr = kb + (size_t)s_off[j] * Cdim;
        float4 k0 = *(const float4*)(kr + lane * 4);
        float4 k1 = *(const float4*)(kr + 128 + lane * 4);
        float p[4];
        #pragma unroll
        for (int t = 0; t < 4; ++t) {
            float s = k0.x * qa[t].x;
            s = fmaf(k0.y, qa[t].y, s); s = fmaf(k0.z, qa[t].z, s); s = fmaf(k0.w, qa[t].w, s);
            s = fmaf(k1.x, qb[t].x, s); s = fmaf(k1.y, qb[t].y, s);
            s = fmaf(k1.z, qb[t].z, s); s = fmaf(k1.w, qb[t].w, s);
            p[t] = s;
        }
        float uA = b1 ? p[1] : p[0], wA = b1 ? p[0] : p[1];
        uA += __shfl_xor_sync(0xffffffffu, wA, 1);
        float uB = b1 ? p[3] : p[2], wB = b1 ? p[2] : p[3];
        uB += __shfl_xor_sync(0xffffffffu, wB, 1);
        float v = b2 ? uB : uA, xx = b2 ? uA : uB;
        v += __shfl_xor_sync(0xffffffffu, xx, 2);
        v += __shfl_xor_sync(0xffffffffu, v, 4);
        v += __shfl_xor_sync(0xffffffffu, v, 8);
        v += __shfl_xor_sync(0xffffffffu, v, 16);
        int aux = s_aux[j];
        int a = aux >> 8;
        int dw = ((aux & 255) - tq) & 255;
        bool valid = (dw <= a) || (dw >= 256 - a);
        v = valid ? v : -1e30f;
        if (lane < 4) s_alpha[j * 4 + lane] = v;
        lmax = fmaxf(lmax, v);
    }
    if (lane < 4) s_red[warp * 4 + lane] = lmax;
    __syncthreads();
    if (tid < 4) {
        float m = s_red[tid];
        #pragma unroll
        for (int w = 1; w < 8; ++w) m = fmaxf(m, s_red[w * 4 + tid]);
        s_m[tid] = m;
    }
    __syncthreads();

    float mt = s_m[tid & 3];
    float dloc = 0.f;
    for (int idx = tid; idx < ncol * 4; idx += 256) {
        int j = idx >> 2;
        float a = __expf(s_alpha[idx] - mt) * qw_lat[s_off[j] >> 8];
        s_alpha[idx] = a;
        dloc += a;
    }
    dloc += __shfl_xor_sync(0xffffffffu, dloc, 4);
    dloc += __shfl_xor_sync(0xffffffffu, dloc, 8);
    dloc += __shfl_xor_sync(0xffffffffu, dloc, 16);
    if (lane < 4) s_red[warp * 4 + lane] = dloc;
    __syncthreads();
    if (tid < 32) {
        float v = s_red[tid];
        v += __shfl_xor_sync(0xffffffffu, v, 4);
        v += __shfl_xor_sync(0xffffffffu, v, 8);
        v += __shfl_xor_sync(0xffffffffu, v, 16);
        if (tid < 4) s_inv[tid] = 1.0f / v;
    }
    __syncthreads();

    int g = tid >> 6;
    int c4 = (tid & 63) * 4;
    const float* vb = g_v + (size_t)b * HWsz * Cdim + c4;
    float4 A0 = {0,0,0,0}, A1 = {0,0,0,0}, A2 = {0,0,0,0}, A3 = {0,0,0,0};
    #pragma unroll 2
    for (int j = g; j < ncol; j += 4) {
        float4 al = *(const float4*)&s_alpha[j * 4];
        const float4 vv = *(const float4*)(vb + (size_t)s_off[j] * Cdim);
        A0.x = fmaf(al.x, vv.x, A0.x); A0.y = fmaf(al.x, vv.y, A0.y);
        A0.z = fmaf(al.x, vv.z, A0.z); A0.w = fmaf(al.x, vv.w, A0.w);
        A1.x = fmaf(al.y, vv.x, A1.x); A1.y = fmaf(al.y, vv.y, A1.y);
        A1.z = fmaf(al.y, vv.z, A1.z); A1.w = fmaf(al.y, vv.w, A1.w);
        A2.x = fmaf(al.z, vv.x, A2.x); A2.y = fmaf(al.z, vv.y, A2.y);
        A2.z = fmaf(al.z, vv.z, A2.z); A2.w = fmaf(al.z, vv.w, A2.w);
        A3.x = fmaf(al.w, vv.x, A3.x); A3.y = fmaf(al.w, vv.y, A3.y);
        A3.z = fmaf(al.w, vv.z, A3.z); A3.w = fmaf(al.w, vv.w, A3.w);
    }
    __syncthreads();
    float* sp = s_alpha;
    *(float4*)&sp[(0 * 4 + g) * 256 + c4] = A0;
    *(float4*)&sp[(1 * 4 + g) * 256 + c4] = A1;
    *(float4*)&sp[(2 * 4 + g) * 256 + c4] = A2;
    *(float4*)&sp[(3 * 4 + g) * 256 + c4] = A3;
    __syncthreads();

    float4 o;
    {
        float v0 = sp[(0*4+0)*256+tid] + sp[(0*4+1)*256+tid] + sp[(0*4+2)*256+tid] + sp[(0*4+3)*256+tid];
        float v1 = sp[(1*4+0)*256+tid] + sp[(1*4+1)*256+tid] + sp[(1*4+2)*256+tid] + sp[(1*4+3)*256+tid];
        float v2 = sp[(2*4+0)*256+tid] + sp[(2*4+1)*256+tid] + sp[(2*4+2)*256+tid] + sp[(2*4+3)*256+tid];
        float v3 = sp[(3*4+0)*256+tid] + sp[(3*4+1)*256+tid] + sp[(3*4+2)*256+tid] + sp[(3*4+3)*256+tid];
        o.x = v0 * s_inv[0]; o.y = v1 * s_inv[1]; o.z = v2 * s_inv[2]; o.w = v3 * s_inv[3];
    }
    *(float4*)(out + (((size_t)b * Cdim + tid) * Hlat + ho) * Wlon + wo0) = o;
}

// ---------------------------------------------------------------------------
extern "C" void kernel_launch(void* const* d_in, const int* in_sizes, int n_in,
                              void* d_out, int out_size) {
    const float* query = (const float*)d_in[0];
    const float* wq    = (const float*)d_in[1];
    const float* wk    = (const float*)d_in[2];
    const float* wv    = (const float*)d_in[3];
    const float* bq    = (const float*)d_in[4];
    const float* bk    = (const float*)d_in[5];
    const float* bv    = (const float*)d_in[6];
    const float* qw    = (const float*)d_in[7];
    const int*   rows  = (const int*)d_in[8];
    const int*   cols  = (const int*)d_in[9];
    int nnz = in_sizes[8];
    float* out = (float*)d_out;

    cudaFuncSetAttribute(qkv_mma_kernel,
                         cudaFuncAttributeMaxDynamicSharedMemorySize, GEMM_SMEM);

    zero_cnt_kernel<<<Hlat * Hlat / 256, 256>>>();
    count_kernel<<<(nnz + 255) / 256, 256>>>(rows, cols, nnz);
    arc_kernel<<<Hlat * Hlat / 256, 256>>>();
    qkv_mma_kernel<<<dim3(HWsz / 128, 12, Bdim), 256, GEMM_SMEM>>>(
        query, wq, wk, wv, bq, bk, bv);
    attn_kernel<<<dim3(Wlon / 4, Hlat, Bdim), 256>>>(qw, out);
}

// round 14
// speedup vs baseline: 1.1393x; 1.0060x over previous
#include <cuda_runtime.h>
#include <cuda_bf16.h>
#include <math.h>
#include <stdint.h>

#define Bdim 2
#define Hlat 128
#define Wlon 256
#define Cdim 256
#define HWsz (Hlat*Wlon)
#define MAXCOL 1536

// Scratch (allocation-free rule: __device__ globals)
__device__ float g_q[(size_t)Bdim*HWsz*Cdim];   // (b,h,w,c), pre-scaled by 1/16
__device__ float g_k[(size_t)Bdim*HWsz*Cdim];
__device__ float g_v[(size_t)Bdim*HWsz*Cdim];
__device__ int   g_cnt[Hlat*Hlat];
__device__ int   g_arc[Hlat*Hlat];
// Precomputed bf16 hi/lo operands for the QKV GEMM
__device__ unsigned short g_xhi[(size_t)Bdim*Cdim*HWsz];
__device__ unsigned short g_xlo[(size_t)Bdim*Cdim*HWsz];
__device__ unsigned short g_whi[3*Cdim*Cdim];
__device__ unsigned short g_wlo[3*Cdim*Cdim];

// ---------------------------------------------------------------------------
// Helpers (sm_80-baseline PTX)
// ---------------------------------------------------------------------------
__device__ __forceinline__ uint32_t smem_u32(const void* p) {
    uint32_t a;
    asm("{ .reg .u64 t; cvta.to.shared.u64 t, %1; cvt.u32.u64 %0, t; }" : "=r"(a) : "l"(p));
    return a;
}
__device__ __forceinline__ void ldsm_x4(uint32_t* r, uint32_t addr) {
    asm volatile("ldmatrix.sync.aligned.m8n8.x4.shared.b16 {%0,%1,%2,%3}, [%4];"
        : "=r"(r[0]), "=r"(r[1]), "=r"(r[2]), "=r"(r[3]) : "r"(addr));
}
__device__ __forceinline__ void ldsm_x4t(uint32_t* r, uint32_t addr) {
    asm volatile("ldmatrix.sync.aligned.m8n8.x4.trans.shared.b16 {%0,%1,%2,%3}, [%4];"
        : "=r"(r[0]), "=r"(r[1]), "=r"(r[2]), "=r"(r[3]) : "r"(addr));
}
__device__ __forceinline__ void mma_bf(float* d, const uint32_t* a, uint32_t b0, uint32_t b1) {
    asm volatile(
        "mma.sync.aligned.m16n8k16.row.col.f32.bf16.bf16.f32 "
        "{%0,%1,%2,%3}, {%4,%5,%6,%7}, {%8,%9}, {%0,%1,%2,%3};"
        : "+f"(d[0]), "+f"(d[1]), "+f"(d[2]), "+f"(d[3])
        : "r"(a[0]), "r"(a[1]), "r"(a[2]), "r"(a[3]), "r"(b0), "r"(b1));
}
__device__ __forceinline__ uint32_t packbf(float lo, float hi) {
    uint32_t r;
    asm("cvt.rn.bf16x2.f32 %0, %1, %2;" : "=r"(r) : "f"(hi), "f"(lo));
    return r;
}
__device__ __forceinline__ float bflo_f(uint32_t h) { return __uint_as_float(h << 16); }
__device__ __forceinline__ float bfhi_f(uint32_t h) { return __uint_as_float(h & 0xffff0000u); }
__device__ __forceinline__ void cp_async16(uint32_t dst, const void* src) {
    asm volatile("cp.async.cg.shared.global [%0], [%1], 16;" :: "r"(dst), "l"(src));
}
__device__ __forceinline__ void cp_commit() {
    asm volatile("cp.async.commit_group;" ::: "memory");
}
__device__ __forceinline__ void cp_wait1() {
    asm volatile("cp.async.wait_group 1;" ::: "memory");
}
__device__ __forceinline__ void cp_wait0() {
    asm volatile("cp.async.wait_group 0;" ::: "memory");
}

// ---------------------------------------------------------------------------
// Arc table precompute
// ---------------------------------------------------------------------------
__global__ void zero_cnt_kernel() { g_cnt[blockIdx.x * 256 + threadIdx.x] = 0; }
__global__ void count_kernel(const int* __restrict__ rows, const int* __restrict__ cols, int nnz) {
    int i = blockIdx.x * 256 + threadIdx.x;
    if (i >= nnz) return;
    atomicAdd(&g_cnt[rows[i] * Hlat + (cols[i] >> 8)], 1);
}
__global__ void arc_kernel() {
    int i = blockIdx.x * 256 + threadIdx.x;
    int c = g_cnt[i];
    g_arc[i] = (c == 0) ? -1 : ((c >= 256) ? 128 : ((c - 1) >> 1));
}

// ---------------------------------------------------------------------------
// One-time bf16 hi/lo conversion (removes 12x/16x redundant convert in GEMM)
// ---------------------------------------------------------------------------
__global__ __launch_bounds__(256) void convert_x_kernel(const float* __restrict__ x) {
    size_t i = (size_t)blockIdx.x * 256 + threadIdx.x;   // float4 index
    float4 v = ((const float4*)x)[i];
    uint32_t h0 = packbf(v.x, v.y), h1 = packbf(v.z, v.w);
    float lx = v.x - bflo_f(h0), ly = v.y - bfhi_f(h0);
    float lz = v.z - bflo_f(h1), lw = v.w - bfhi_f(h1);
    ((uint2*)g_xhi)[i] = make_uint2(h0, h1);
    ((uint2*)g_xlo)[i] = make_uint2(packbf(lx, ly), packbf(lz, lw));
}
__global__ __launch_bounds__(256) void convert_w_kernel(
    const float* __restrict__ wq, const float* __restrict__ wk, const float* __restrict__ wv) {
    int i = blockIdx.x * 256 + threadIdx.x;              // float4 index, 0..49151
    int mat = i >> 14, r = i & 16383;
    const float* W = (mat == 0) ? wq : (mat == 1) ? wk : wv;
    float4 v = ((const float4*)W)[r];
    uint32_t h0 = packbf(v.x, v.y), h1 = packbf(v.z, v.w);
    float lx = v.x - bflo_f(h0), ly = v.y - bfhi_f(h0);
    float lz = v.z - bflo_f(h1), lw = v.w - bfhi_f(h1);
    ((uint2*)g_whi)[mat * 16384 + r] = make_uint2(h0, h1);
    ((uint2*)g_wlo)[mat * 16384 + r] = make_uint2(packbf(lx, ly), packbf(lz, lw));
}

// ---------------------------------------------------------------------------
// QKV projection: mma.sync bf16 hi/lo (3-term); cp.async DIRECTLY into
// ldmatrix-ready padded tiles (no convert pass). Double-buffered.
// Per-buffer layout (bytes): AHI@0 (8704), ALO@8704, WHI@17408 (5120), WLO@22528
// ---------------------------------------------------------------------------
#define BUFST     27648
#define GEMM_SMEM (2*BUFST)   // 55296

__global__ __launch_bounds__(256, 3) void qkv_mma_kernel(
    const float* __restrict__ bq, const float* __restrict__ bk, const float* __restrict__ bv)
{
    extern __shared__ char dsm[];
    uint32_t sb = smem_u32(dsm);

    int tid = threadIdx.x, lane = tid & 31, warp = tid >> 5;
    int p0 = blockIdx.x * 128;
    int nb = blockIdx.y;
    int b  = blockIdx.z;
    int mat = nb >> 2;
    int j0 = (nb & 3) * 64;

    const float* Bias = (mat == 0) ? bq : (mat == 1) ? bk : bv;
    float*       Out  = (mat == 0) ? g_q : (mat == 1) ? g_k : g_v;
    float osc = (mat == 0) ? 0.0625f : 1.0f;

    const unsigned short* xh = g_xhi + (size_t)b * Cdim * HWsz;
    const unsigned short* xl = g_xlo + (size_t)b * Cdim * HWsz;

    float acc[2][4][4];
    #pragma unroll
    for (int i = 0; i < 2; ++i)
        #pragma unroll
        for (int j = 0; j < 4; ++j)
            #pragma unroll
            for (int k = 0; k < 4; ++k) acc[i][j][k] = 0.f;

    int wp = warp & 3, wj = warp >> 2;
    int g  = lane >> 3, jl = lane & 7;
    int a_krow = jl + ((g & 2) ? 8 : 0);
    int a_mcol = (g & 1) ? 8 : 0;
    int b_nrow = jl + ((g & 2) ? 8 : 0);
    int b_kcol = (g & 1) ? 8 : 0;

    auto prefetch = [&](int chunk, int buf) {
        int c0 = chunk * 32;
        uint32_t base = sb + buf * BUFST;
        #pragma unroll
        for (int it = 0; it < 2; ++it) {
            int idx = tid + it * 256;          // 0..511
            int r = idx >> 4, i = idx & 15;
            size_t src = (size_t)(c0 + r) * HWsz + p0 + i * 8;
            cp_async16(base + r * 272 + i * 16, xh + src);
            cp_async16(base + 8704 + r * 272 + i * 16, xl + src);
        }
        {
            int j = tid >> 2, i = tid & 3;
            size_t ws = (size_t)mat * 65536 + (size_t)(j0 + j) * 256 + c0 + i * 8;
            cp_async16(base + 17408 + j * 80 + i * 16, g_whi + ws);
            cp_async16(base + 22528 + j * 80 + i * 16, g_wlo + ws);
        }
    };

    prefetch(0, 0);
    cp_commit();

    for (int chunk = 0; chunk < 8; ++chunk) {
        int buf = chunk & 1;
        __syncthreads();   // all warps done with mma on buf^1 before overwrite
        if (chunk < 7) {
            prefetch(chunk + 1, buf ^ 1);
            cp_commit();
            cp_wait1();
        } else {
            cp_wait0();
        }
        __syncthreads();   // chunk's tiles visible to all warps

        uint32_t ah_b = sb + buf * BUFST;
        uint32_t al_b = ah_b + 8704;
        uint32_t wh_b = ah_b + 17408;
        uint32_t wl_b = ah_b + 22528;

        #pragma unroll
        for (int ks = 0; ks < 2; ++ks) {
            int k0 = ks * 16;
            uint32_t ah[2][4], al[2][4];
            #pragma unroll
            for (int mt = 0; mt < 2; ++mt) {
                int m0 = wp * 32 + mt * 16;
                uint32_t off = (uint32_t)((k0 + a_krow) * 272 + (m0 + a_mcol) * 2);
                ldsm_x4t(ah[mt], ah_b + off);
                ldsm_x4t(al[mt], al_b + off);
            }
            #pragma unroll
            for (int np = 0; np < 2; ++np) {
                int n0 = wj * 32 + np * 16;
                uint32_t off = (uint32_t)((n0 + b_nrow) * 80 + (k0 + b_kcol) * 2);
                uint32_t bh[4], bl[4];
                ldsm_x4(bh, wh_b + off);
                ldsm_x4(bl, wl_b + off);
                #pragma unroll
                for (int mt = 0; mt < 2; ++mt) {
                    mma_bf(acc[mt][np * 2],     ah[mt], bh[0], bh[1]);
                    mma_bf(acc[mt][np * 2],     al[mt], bh[0], bh[1]);
                    mma_bf(acc[mt][np * 2],     ah[mt], bl[0], bl[1]);
                    mma_bf(acc[mt][np * 2 + 1], ah[mt], bh[2], bh[3]);
                    mma_bf(acc[mt][np * 2 + 1], al[mt], bh[2], bh[3]);
                    mma_bf(acc[mt][np * 2 + 1], ah[mt], bl[2], bl[3]);
                }
            }
        }
    }

    float* opb = Out + (size_t)b * HWsz * Cdim;
    int r0 = lane >> 2, cp = (lane & 3) * 2;
    #pragma unroll
    for (int mt = 0; mt < 2; ++mt) {
        int p = p0 + wp * 32 + mt * 16 + r0;
        #pragma unroll
        for (int nt = 0; nt < 4; ++nt) {
            int jc = j0 + wj * 32 + nt * 8 + cp;
            float b0v = Bias[jc], b1v = Bias[jc + 1];
            float2 s0, s1;
            s0.x = fmaf(acc[mt][nt][0], osc, b0v);
            s0.y = fmaf(acc[mt][nt][1], osc, b1v);
            s1.x = fmaf(acc[mt][nt][2], osc, b0v);
            s1.y = fmaf(acc[mt][nt][3], osc, b1v);
            *(float2*)(opb + (size_t)p * Cdim + jc) = s0;
            *(float2*)(opb + (size_t)(p + 8) * Cdim + jc) = s1;
        }
    }
}

// ---------------------------------------------------------------------------
// Attention over distinct columns, T=4 (measured-best config, ~815 us).
// ---------------------------------------------------------------------------
__global__ __launch_bounds__(256) void attn_kernel(
    const float* __restrict__ qw_lat,
    float* __restrict__ out)
{
    __shared__ __align__(16) float s_q[4][Cdim];
    __shared__ __align__(16) float s_alpha[MAXCOL * 4];
    __shared__ __align__(16) int   s_off[MAXCOL];
    __shared__ __align__(16) int   s_aux[MAXCOL];
    __shared__ int   s_arcv[Hlat];
    __shared__ int   s_wid[Hlat];
    __shared__ int   s_start[Hlat + 1];
    __shared__ float s_red[32];
    __shared__ float s_m[4];
    __shared__ float s_inv[4];

    int wo0 = blockIdx.x * 4;
    int ho = blockIdx.y, b = blockIdx.z;
    int tid = threadIdx.x, lane = tid & 31, warp = tid >> 5;

    if (tid < Hlat) {
        int a = g_arc[ho * Hlat + tid];
        s_arcv[tid] = a;
        int w = (a < 0) ? 0 : (2 * a + 4);
        s_wid[tid] = (w > 256) ? 256 : w;
    }
    {
        int t = tid >> 6; int c4 = (tid & 63) * 4;
        *(float4*)&s_q[t][c4] =
            *(const float4*)(g_q + (((size_t)b * Hlat + ho) * Wlon + wo0 + t) * Cdim + c4);
    }
    __syncthreads();

    if (warp == 0) {
        int b0 = lane * 4;
        int w0 = s_wid[b0], w1 = s_wid[b0 + 1], w2 = s_wid[b0 + 2], w3 = s_wid[b0 + 3];
        int p1 = w0 + w1, p2 = p1 + w2, tot = p2 + w3;
        int inc = tot;
        #pragma unroll
        for (int o = 1; o < 32; o <<= 1) {
            int nv = __shfl_up_sync(0xffffffffu, inc, o);
            if (lane >= o) inc += nv;
        }
        int base = inc - tot;
        s_start[b0] = base; s_start[b0 + 1] = base + w0;
        s_start[b0 + 2] = base + p1; s_start[b0 + 3] = base + p2;
        if (lane == 31) s_start[Hlat] = inc;
    }
    __syncthreads();
    int ncol = s_start[Hlat];
    if (ncol > MAXCOL) ncol = MAXCOL;

    for (int j = tid; j < ncol; j += 256) {
        int lo = 0, hi2 = Hlat;
        while (lo + 1 < hi2) {
            int mid = (lo + hi2) >> 1;
            if (s_start[mid] <= j) lo = mid; else hi2 = mid;
        }
        int a = s_arcv[lo];
        int w = wo0 - a + (j - s_start[lo]);
        s_off[j] = lo * 256 + (w & 255);
        s_aux[j] = (a << 8) | ((w - wo0) & 255);
    }
    __syncthreads();

    const int tq = lane & 3;
    float4 qa[4], qb[4];
    #pragma unroll
    for (int t = 0; t < 4; ++t) {
        qa[t] = *(const float4*)&s_q[t][lane * 4];
        qb[t] = *(const float4*)&s_q[t][128 + lane * 4];
    }
    const float* kb = g_k + (size_t)b * HWsz * Cdim;
    bool b1 = (lane & 1), b2 = (lane & 2);
    float lmax = -INFINITY;

    #pragma unroll 2
    for (int j = warp; j < ncol; j += 8) {
        const float* kr = kb + (size_t)s_off[j] * Cdim;
        float4 k0 = *(const float4*)(kr + lane * 4);
        float4 k1 = *(const float4*)(kr + 128 + lane * 4);
        float p[4];
        #pragma unroll
        for (int t = 0; t < 4; ++t) {
            float s = k0.x * qa[t].x;
            s = fmaf(k0.y, qa[t].y, s); s = fmaf(k0.z, qa[t].z, s); s = fmaf(k0.w, qa[t].w, s);
            s = fmaf(k1.x, qb[t].x, s); s = fmaf(k1.y, qb[t].y, s);
            s = fmaf(k1.z, qb[t].z, s); s = fmaf(k1.w, qb[t].w, s);
            p[t] = s;
        }
        float uA = b1 ? p[1] : p[0], wA = b1 ? p[0] : p[1];
        uA += __shfl_xor_sync(0xffffffffu, wA, 1);
        float uB = b1 ? p[3] : p[2], wB = b1 ? p[2] : p[3];
        uB += __shfl_xor_sync(0xffffffffu, wB, 1);
        float v = b2 ? uB : uA, xx = b2 ? uA : uB;
        v += __shfl_xor_sync(0xffffffffu, xx, 2);
        v += __shfl_xor_sync(0xffffffffu, v, 4);
        v += __shfl_xor_sync(0xffffffffu, v, 8);
        v += __shfl_xor_sync(0xffffffffu, v, 16);
        int aux = s_aux[j];
        int a = aux >> 8;
        int dw = ((aux & 255) - tq) & 255;
        bool valid = (dw <= a) || (dw >= 256 - a);
        v = valid ? v : -1e30f;
        if (lane < 4) s_alpha[j * 4 + lane] = v;
        lmax = fmaxf(lmax, v);
    }
    if (lane < 4) s_red[warp * 4 + lane] = lmax;
    __syncthreads();
    if (tid < 4) {
        float m = s_red[tid];
        #pragma unroll
        for (int w = 1; w < 8; ++w) m = fmaxf(m, s_red[w * 4 + tid]);
        s_m[tid] = m;
    }
    __syncthreads();

    float mt = s_m[tid & 3];
    float dloc = 0.f;
    for (int idx = tid; idx < ncol * 4; idx += 256) {
        int j = idx >> 2;
        float a = __expf(s_alpha[idx] - mt) * qw_lat[s_off[j] >> 8];
        s_alpha[idx] = a;
        dloc += a;
    }
    dloc += __shfl_xor_sync(0xffffffffu, dloc, 4);
    dloc += __shfl_xor_sync(0xffffffffu, dloc, 8);
    dloc += __shfl_xor_sync(0xffffffffu, dloc, 16);
    if (lane < 4) s_red[warp * 4 + lane] = dloc;
    __syncthreads();
    if (tid < 32) {
        float v = s_red[tid];
        v += __shfl_xor_sync(0xffffffffu, v, 4);
        v += __shfl_xor_sync(0xffffffffu, v, 8);
        v += __shfl_xor_sync(0xffffffffu, v, 16);
        if (tid < 4) s_inv[tid] = 1.0f / v;
    }
    __syncthreads();

    int g = tid >> 6;
    int c4 = (tid & 63) * 4;
    const float* vb = g_v + (size_t)b * HWsz * Cdim + c4;
    float4 A0 = {0,0,0,0}, A1 = {0,0,0,0}, A2 = {0,0,0,0}, A3 = {0,0,0,0};
    #pragma unroll 2
    for (int j = g; j < ncol; j += 4) {
        float4 al = *(const float4*)&s_alpha[j * 4];
        const float4 vv = *(const float4*)(vb + (size_t)s_off[j] * Cdim);
        A0.x = fmaf(al.x, vv.x, A0.x); A0.y = fmaf(al.x, vv.y, A0.y);
        A0.z = fmaf(al.x, vv.z, A0.z); A0.w = fmaf(al.x, vv.w, A0.w);
        A1.x = fmaf(al.y, vv.x, A1.x); A1.y = fmaf(al.y, vv.y, A1.y);
        A1.z = fmaf(al.y, vv.z, A1.z); A1.w = fmaf(al.y, vv.w, A1.w);
        A2.x = fmaf(al.z, vv.x, A2.x); A2.y = fmaf(al.z, vv.y, A2.y);
        A2.z = fmaf(al.z, vv.z, A2.z); A2.w = fmaf(al.z, vv.w, A2.w);
        A3.x = fmaf(al.w, vv.x, A3.x); A3.y = fmaf(al.w, vv.y, A3.y);
        A3.z = fmaf(al.w, vv.z, A3.z); A3.w = fmaf(al.w, vv.w, A3.w);
    }
    __syncthreads();
    float* sp = s_alpha;
    *(float4*)&sp[(0 * 4 + g) * 256 + c4] = A0;
    *(float4*)&sp[(1 * 4 + g) * 256 + c4] = A1;
    *(float4*)&sp[(2 * 4 + g) * 256 + c4] = A2;
    *(float4*)&sp[(3 * 4 + g) * 256 + c4] = A3;
    __syncthreads();

    float4 o;
    {
        float v0 = sp[(0*4+0)*256+tid] + sp[(0*4+1)*256+tid] + sp[(0*4+2)*256+tid] + sp[(0*4+3)*256+tid];
        float v1 = sp[(1*4+0)*256+tid] + sp[(1*4+1)*256+tid] + sp[(1*4+2)*256+tid] + sp[(1*4+3)*256+tid];
        float v2 = sp[(2*4+0)*256+tid] + sp[(2*4+1)*256+tid] + sp[(2*4+2)*256+tid] + sp[(2*4+3)*256+tid];
        float v3 = sp[(3*4+0)*256+tid] + sp[(3*4+1)*256+tid] + sp[(3*4+2)*256+tid] + sp[(3*4+3)*256+tid];
        o.x = v0 * s_inv[0]; o.y = v1 * s_inv[1]; o.z = v2 * s_inv[2]; o.w = v3 * s_inv[3];
    }
    *(float4*)(out + (((size_t)b * Cdim + tid) * Hlat + ho) * Wlon + wo0) = o;
}

// ---------------------------------------------------------------------------
extern "C" void kernel_launch(void* const* d_in, const int* in_sizes, int n_in,
                              void* d_out, int out_size) {
    const float* query = (const float*)d_in[0];
    const float* wq    = (const float*)d_in[1];
    const float* wk    = (const float*)d_in[2];
    const float* wv    = (const float*)d_in[3];
    const float* bq    = (const float*)d_in[4];
    const float* bk    = (const float*)d_in[5];
    const float* bv    = (const float*)d_in[6];
    const float* qw    = (const float*)d_in[7];
    const int*   rows  = (const int*)d_in[8];
    const int*   cols  = (const int*)d_in[9];
    int nnz = in_sizes[8];
    float* out = (float*)d_out;

    cudaFuncSetAttribute(qkv_mma_kernel,
                         cudaFuncAttributeMaxDynamicSharedMemorySize, GEMM_SMEM);

    zero_cnt_kernel<<<Hlat * Hlat / 256, 256>>>();
    count_kernel<<<(nnz + 255) / 256, 256>>>(rows, cols, nnz);
    arc_kernel<<<Hlat * Hlat / 256, 256>>>();
    convert_x_kernel<<<(Bdim * Cdim * HWsz / 4) / 256, 256>>>(query);
    convert_w_kernel<<<(3 * Cdim * Cdim / 4) / 256, 256>>>(wq, wk, wv);
    qkv_mma_kernel<<<dim3(HWsz / 128, 12, Bdim), 256, GEMM_SMEM>>>(bq, bk, bv);
    attn_kernel<<<dim3(Wlon / 4, Hlat, Bdim), 256>>>(qw, out);
}

// round 15
// speedup vs baseline: 1.1947x; 1.0486x over previous
#include <cuda_runtime.h>
#include <cuda_bf16.h>
#include <math.h>
#include <stdint.h>

#define Bdim 2
#define Hlat 128
#define Wlon 256
#define Cdim 256
#define HWsz (Hlat*Wlon)
#define MAXCOL 1536

// Scratch (allocation-free rule: __device__ globals)
__device__ float g_q[(size_t)Bdim*HWsz*Cdim];   // (b,h,w,c), pre-scaled by 1/16
__device__ float g_k[(size_t)Bdim*HWsz*Cdim];
__device__ float g_v[(size_t)Bdim*HWsz*Cdim];
__device__ int   g_cnt[Hlat*Hlat];
__device__ int   g_arc[Hlat*Hlat];
// Precomputed bf16 hi/lo operands for the QKV GEMM
__device__ unsigned short g_xhi[(size_t)Bdim*Cdim*HWsz];
__device__ unsigned short g_xlo[(size_t)Bdim*Cdim*HWsz];
__device__ unsigned short g_whi[3*Cdim*Cdim];
__device__ unsigned short g_wlo[3*Cdim*Cdim];

// ---------------------------------------------------------------------------
// Helpers (sm_80-baseline PTX)
// ---------------------------------------------------------------------------
__device__ __forceinline__ uint32_t smem_u32(const void* p) {
    uint32_t a;
    asm("{ .reg .u64 t; cvta.to.shared.u64 t, %1; cvt.u32.u64 %0, t; }" : "=r"(a) : "l"(p));
    return a;
}
__device__ __forceinline__ void ldsm_x4(uint32_t* r, uint32_t addr) {
    asm volatile("ldmatrix.sync.aligned.m8n8.x4.shared.b16 {%0,%1,%2,%3}, [%4];"
        : "=r"(r[0]), "=r"(r[1]), "=r"(r[2]), "=r"(r[3]) : "r"(addr));
}
__device__ __forceinline__ void ldsm_x4t(uint32_t* r, uint32_t addr) {
    asm volatile("ldmatrix.sync.aligned.m8n8.x4.trans.shared.b16 {%0,%1,%2,%3}, [%4];"
        : "=r"(r[0]), "=r"(r[1]), "=r"(r[2]), "=r"(r[3]) : "r"(addr));
}
__device__ __forceinline__ void mma_bf(float* d, const uint32_t* a, uint32_t b0, uint32_t b1) {
    asm volatile(
        "mma.sync.aligned.m16n8k16.row.col.f32.bf16.bf16.f32 "
        "{%0,%1,%2,%3}, {%4,%5,%6,%7}, {%8,%9}, {%0,%1,%2,%3};"
        : "+f"(d[0]), "+f"(d[1]), "+f"(d[2]), "+f"(d[3])
        : "r"(a[0]), "r"(a[1]), "r"(a[2]), "r"(a[3]), "r"(b0), "r"(b1));
}
__device__ __forceinline__ uint32_t packbf(float lo, float hi) {
    uint32_t r;
    asm("cvt.rn.bf16x2.f32 %0, %1, %2;" : "=r"(r) : "f"(hi), "f"(lo));
    return r;
}
__device__ __forceinline__ float bflo_f(uint32_t h) { return __uint_as_float(h << 16); }
__device__ __forceinline__ float bfhi_f(uint32_t h) { return __uint_as_float(h & 0xffff0000u); }
__device__ __forceinline__ void cp_async16(uint32_t dst, const void* src) {
    asm volatile("cp.async.cg.shared.global [%0], [%1], 16;" :: "r"(dst), "l"(src));
}
__device__ __forceinline__ void cp_commit() {
    asm volatile("cp.async.commit_group;" ::: "memory");
}
__device__ __forceinline__ void cp_wait1() {
    asm volatile("cp.async.wait_group 1;" ::: "memory");
}
__device__ __forceinline__ void cp_wait0() {
    asm volatile("cp.async.wait_group 0;" ::: "memory");
}

// ---------------------------------------------------------------------------
// Arc table precompute
// ---------------------------------------------------------------------------
__global__ void zero_cnt_kernel() { g_cnt[blockIdx.x * 256 + threadIdx.x] = 0; }
__global__ void count_kernel(const int* __restrict__ rows, const int* __restrict__ cols, int nnz) {
    int i = blockIdx.x * 256 + threadIdx.x;
    if (i >= nnz) return;
    atomicAdd(&g_cnt[rows[i] * Hlat + (cols[i] >> 8)], 1);
}
__global__ void arc_kernel() {
    int i = blockIdx.x * 256 + threadIdx.x;
    int c = g_cnt[i];
    g_arc[i] = (c == 0) ? -1 : ((c >= 256) ? 128 : ((c - 1) >> 1));
}

// ---------------------------------------------------------------------------
// One-time bf16 hi/lo conversion
// ---------------------------------------------------------------------------
__global__ __launch_bounds__(256) void convert_x_kernel(const float* __restrict__ x) {
    size_t i = (size_t)blockIdx.x * 256 + threadIdx.x;   // float4 index
    float4 v = ((const float4*)x)[i];
    uint32_t h0 = packbf(v.x, v.y), h1 = packbf(v.z, v.w);
    float lx = v.x - bflo_f(h0), ly = v.y - bfhi_f(h0);
    float lz = v.z - bflo_f(h1), lw = v.w - bfhi_f(h1);
    ((uint2*)g_xhi)[i] = make_uint2(h0, h1);
    ((uint2*)g_xlo)[i] = make_uint2(packbf(lx, ly), packbf(lz, lw));
}
__global__ __launch_bounds__(256) void convert_w_kernel(
    const float* __restrict__ wq, const float* __restrict__ wk, const float* __restrict__ wv) {
    int i = blockIdx.x * 256 + threadIdx.x;              // float4 index, 0..49151
    int mat = i >> 14, r = i & 16383;
    const float* W = (mat == 0) ? wq : (mat == 1) ? wk : wv;
    float4 v = ((const float4*)W)[r];
    uint32_t h0 = packbf(v.x, v.y), h1 = packbf(v.z, v.w);
    float lx = v.x - bflo_f(h0), ly = v.y - bfhi_f(h0);
    float lz = v.z - bflo_f(h1), lw = v.w - bfhi_f(h1);
    ((uint2*)g_whi)[mat * 16384 + r] = make_uint2(h0, h1);
    ((uint2*)g_wlo)[mat * 16384 + r] = make_uint2(packbf(lx, ly), packbf(lz, lw));
}

// ---------------------------------------------------------------------------
// QKV projection: mma.sync bf16 hi/lo (3-term); cp.async into ldmatrix-ready
// padded tiles. Double-buffered. (Round-14 config, ~237 us.)
// ---------------------------------------------------------------------------
#define BUFST     27648
#define GEMM_SMEM (2*BUFST)   // 55296

__global__ __launch_bounds__(256, 3) void qkv_mma_kernel(
    const float* __restrict__ bq, const float* __restrict__ bk, const float* __restrict__ bv)
{
    extern __shared__ char dsm[];
    uint32_t sb = smem_u32(dsm);

    int tid = threadIdx.x, lane = tid & 31, warp = tid >> 5;
    int p0 = blockIdx.x * 128;
    int nb = blockIdx.y;
    int b  = blockIdx.z;
    int mat = nb >> 2;
    int j0 = (nb & 3) * 64;

    const float* Bias = (mat == 0) ? bq : (mat == 1) ? bk : bv;
    float*       Out  = (mat == 0) ? g_q : (mat == 1) ? g_k : g_v;
    float osc = (mat == 0) ? 0.0625f : 1.0f;

    const unsigned short* xh = g_xhi + (size_t)b * Cdim * HWsz;
    const unsigned short* xl = g_xlo + (size_t)b * Cdim * HWsz;

    float acc[2][4][4];
    #pragma unroll
    for (int i = 0; i < 2; ++i)
        #pragma unroll
        for (int j = 0; j < 4; ++j)
            #pragma unroll
            for (int k = 0; k < 4; ++k) acc[i][j][k] = 0.f;

    int wp = warp & 3, wj = warp >> 2;
    int g  = lane >> 3, jl = lane & 7;
    int a_krow = jl + ((g & 2) ? 8 : 0);
    int a_mcol = (g & 1) ? 8 : 0;
    int b_nrow = jl + ((g & 2) ? 8 : 0);
    int b_kcol = (g & 1) ? 8 : 0;

    auto prefetch = [&](int chunk, int buf) {
        int c0 = chunk * 32;
        uint32_t base = sb + buf * BUFST;
        #pragma unroll
        for (int it = 0; it < 2; ++it) {
            int idx = tid + it * 256;          // 0..511
            int r = idx >> 4, i = idx & 15;
            size_t src = (size_t)(c0 + r) * HWsz + p0 + i * 8;
            cp_async16(base + r * 272 + i * 16, xh + src);
            cp_async16(base + 8704 + r * 272 + i * 16, xl + src);
        }
        {
            int j = tid >> 2, i = tid & 3;
            size_t ws = (size_t)mat * 65536 + (size_t)(j0 + j) * 256 + c0 + i * 8;
            cp_async16(base + 17408 + j * 80 + i * 16, g_whi + ws);
            cp_async16(base + 22528 + j * 80 + i * 16, g_wlo + ws);
        }
    };

    prefetch(0, 0);
    cp_commit();

    for (int chunk = 0; chunk < 8; ++chunk) {
        int buf = chunk & 1;
        __syncthreads();
        if (chunk < 7) {
            prefetch(chunk + 1, buf ^ 1);
            cp_commit();
            cp_wait1();
        } else {
            cp_wait0();
        }
        __syncthreads();

        uint32_t ah_b = sb + buf * BUFST;
        uint32_t al_b = ah_b + 8704;
        uint32_t wh_b = ah_b + 17408;
        uint32_t wl_b = ah_b + 22528;

        #pragma unroll
        for (int ks = 0; ks < 2; ++ks) {
            int k0 = ks * 16;
            uint32_t ah[2][4], al[2][4];
            #pragma unroll
            for (int mt = 0; mt < 2; ++mt) {
                int m0 = wp * 32 + mt * 16;
                uint32_t off = (uint32_t)((k0 + a_krow) * 272 + (m0 + a_mcol) * 2);
                ldsm_x4t(ah[mt], ah_b + off);
                ldsm_x4t(al[mt], al_b + off);
            }
            #pragma unroll
            for (int np = 0; np < 2; ++np) {
                int n0 = wj * 32 + np * 16;
                uint32_t off = (uint32_t)((n0 + b_nrow) * 80 + (k0 + b_kcol) * 2);
                uint32_t bh[4], bl[4];
                ldsm_x4(bh, wh_b + off);
                ldsm_x4(bl, wl_b + off);
                #pragma unroll
                for (int mt = 0; mt < 2; ++mt) {
                    mma_bf(acc[mt][np * 2],     ah[mt], bh[0], bh[1]);
                    mma_bf(acc[mt][np * 2],     al[mt], bh[0], bh[1]);
                    mma_bf(acc[mt][np * 2],     ah[mt], bl[0], bl[1]);
                    mma_bf(acc[mt][np * 2 + 1], ah[mt], bh[2], bh[3]);
                    mma_bf(acc[mt][np * 2 + 1], al[mt], bh[2], bh[3]);
                    mma_bf(acc[mt][np * 2 + 1], ah[mt], bl[2], bl[3]);
                }
            }
        }
    }

    float* opb = Out + (size_t)b * HWsz * Cdim;
    int r0 = lane >> 2, cp = (lane & 3) * 2;
    #pragma unroll
    for (int mt = 0; mt < 2; ++mt) {
        int p = p0 + wp * 32 + mt * 16 + r0;
        #pragma unroll
        for (int nt = 0; nt < 4; ++nt) {
            int jc = j0 + wj * 32 + nt * 8 + cp;
            float b0v = Bias[jc], b1v = Bias[jc + 1];
            float2 s0, s1;
            s0.x = fmaf(acc[mt][nt][0], osc, b0v);
            s0.y = fmaf(acc[mt][nt][1], osc, b1v);
            s1.x = fmaf(acc[mt][nt][2], osc, b0v);
            s1.y = fmaf(acc[mt][nt][3], osc, b1v);
            *(float2*)(opb + (size_t)p * Cdim + jc) = s0;
            *(float2*)(opb + (size_t)(p + 8) * Cdim + jc) = s1;
        }
    }
}

// ---------------------------------------------------------------------------
// Attention over distinct columns, T=4 (measured-best structure) with
// POLE-FIRST ho scheduling: heavy (polar) rows launch first, light rows
// backfill the tail. ho = (y&1) ? 127-(y>>1) : (y>>1).
// ---------------------------------------------------------------------------
__global__ __launch_bounds__(256) void attn_kernel(
    const float* __restrict__ qw_lat,
    float* __restrict__ out)
{
    __shared__ __align__(16) float s_q[4][Cdim];
    __shared__ __align__(16) float s_alpha[MAXCOL * 4];
    __shared__ __align__(16) int   s_off[MAXCOL];
    __shared__ __align__(16) int   s_aux[MAXCOL];
    __shared__ int   s_arcv[Hlat];
    __shared__ int   s_wid[Hlat];
    __shared__ int   s_start[Hlat + 1];
    __shared__ float s_red[32];
    __shared__ float s_m[4];
    __shared__ float s_inv[4];

    int wo0 = blockIdx.x * 4;
    int yy = blockIdx.y;
    int ho = (yy & 1) ? (Hlat - 1 - (yy >> 1)) : (yy >> 1);   // pole-first schedule
    int b = blockIdx.z;
    int tid = threadIdx.x, lane = tid & 31, warp = tid >> 5;

    if (tid < Hlat) {
        int a = g_arc[ho * Hlat + tid];
        s_arcv[tid] = a;
        int w = (a < 0) ? 0 : (2 * a + 4);
        s_wid[tid] = (w > 256) ? 256 : w;
    }
    {
        int t = tid >> 6; int c4 = (tid & 63) * 4;
        *(float4*)&s_q[t][c4] =
            *(const float4*)(g_q + (((size_t)b * Hlat + ho) * Wlon + wo0 + t) * Cdim + c4);
    }
    __syncthreads();

    if (warp == 0) {
        int b0 = lane * 4;
        int w0 = s_wid[b0], w1 = s_wid[b0 + 1], w2 = s_wid[b0 + 2], w3 = s_wid[b0 + 3];
        int p1 = w0 + w1, p2 = p1 + w2, tot = p2 + w3;
        int inc = tot;
        #pragma unroll
        for (int o = 1; o < 32; o <<= 1) {
            int nv = __shfl_up_sync(0xffffffffu, inc, o);
            if (lane >= o) inc += nv;
        }
        int base = inc - tot;
        s_start[b0] = base; s_start[b0 + 1] = base + w0;
        s_start[b0 + 2] = base + p1; s_start[b0 + 3] = base + p2;
        if (lane == 31) s_start[Hlat] = inc;
    }
    __syncthreads();
    int ncol = s_start[Hlat];
    if (ncol > MAXCOL) ncol = MAXCOL;

    for (int j = tid; j < ncol; j += 256) {
        int lo = 0, hi2 = Hlat;
        while (lo + 1 < hi2) {
            int mid = (lo + hi2) >> 1;
            if (s_start[mid] <= j) lo = mid; else hi2 = mid;
        }
        int a = s_arcv[lo];
        int w = wo0 - a + (j - s_start[lo]);
        s_off[j] = lo * 256 + (w & 255);
        s_aux[j] = (a << 8) | ((w - wo0) & 255);
    }
    __syncthreads();

    const int tq = lane & 3;
    float4 qa[4], qb[4];
    #pragma unroll
    for (int t = 0; t < 4; ++t) {
        qa[t] = *(const float4*)&s_q[t][lane * 4];
        qb[t] = *(const float4*)&s_q[t][128 + lane * 4];
    }
    const float* kb = g_k + (size_t)b * HWsz * Cdim;
    bool b1 = (lane & 1), b2 = (lane & 2);
    float lmax = -INFINITY;

    #pragma unroll 4
    for (int j = warp; j < ncol; j += 8) {
        const float* kr = kb + (size_t)s_off[j] * Cdim;
        float4 k0 = *(const float4*)(kr + lane * 4);
        float4 k1 = *(const float4*)(kr + 128 + lane * 4);
        float p[4];
        #pragma unroll
        for (int t = 0; t < 4; ++t) {
            float s = k0.x * qa[t].x;
            s = fmaf(k0.y, qa[t].y, s); s = fmaf(k0.z, qa[t].z, s); s = fmaf(k0.w, qa[t].w, s);
            s = fmaf(k1.x, qb[t].x, s); s = fmaf(k1.y, qb[t].y, s);
            s = fmaf(k1.z, qb[t].z, s); s = fmaf(k1.w, qb[t].w, s);
            p[t] = s;
        }
        float uA = b1 ? p[1] : p[0], wA = b1 ? p[0] : p[1];
        uA += __shfl_xor_sync(0xffffffffu, wA, 1);
        float uB = b1 ? p[3] : p[2], wB = b1 ? p[2] : p[3];
        uB += __shfl_xor_sync(0xffffffffu, wB, 1);
        float v = b2 ? uB : uA, xx = b2 ? uA : uB;
        v += __shfl_xor_sync(0xffffffffu, xx, 2);
        v += __shfl_xor_sync(0xffffffffu, v, 4);
        v += __shfl_xor_sync(0xffffffffu, v, 8);
        v += __shfl_xor_sync(0xffffffffu, v, 16);
        int aux = s_aux[j];
        int a = aux >> 8;
        int dw = ((aux & 255) - tq) & 255;
        bool valid = (dw <= a) || (dw >= 256 - a);
        v = valid ? v : -1e30f;
        if (lane < 4) s_alpha[j * 4 + lane] = v;
        lmax = fmaxf(lmax, v);
    }
    if (lane < 4) s_red[warp * 4 + lane] = lmax;
    __syncthreads();
    if (tid < 4) {
        float m = s_red[tid];
        #pragma unroll
        for (int w = 1; w < 8; ++w) m = fmaxf(m, s_red[w * 4 + tid]);
        s_m[tid] = m;
    }
    __syncthreads();

    float mt = s_m[tid & 3];
    float dloc = 0.f;
    for (int idx = tid; idx < ncol * 4; idx += 256) {
        int j = idx >> 2;
        float a = __expf(s_alpha[idx] - mt) * qw_lat[s_off[j] >> 8];
        s_alpha[idx] = a;
        dloc += a;
    }
    dloc += __shfl_xor_sync(0xffffffffu, dloc, 4);
    dloc += __shfl_xor_sync(0xffffffffu, dloc, 8);
    dloc += __shfl_xor_sync(0xffffffffu, dloc, 16);
    if (lane < 4) s_red[warp * 4 + lane] = dloc;
    __syncthreads();
    if (tid < 32) {
        float v = s_red[tid];
        v += __shfl_xor_sync(0xffffffffu, v, 4);
        v += __shfl_xor_sync(0xffffffffu, v, 8);
        v += __shfl_xor_sync(0xffffffffu, v, 16);
        if (tid < 4) s_inv[tid] = 1.0f / v;
    }
    __syncthreads();

    int g = tid >> 6;
    int c4 = (tid & 63) * 4;
    const float* vb = g_v + (size_t)b * HWsz * Cdim + c4;
    float4 A0 = {0,0,0,0}, A1 = {0,0,0,0}, A2 = {0,0,0,0}, A3 = {0,0,0,0};
    #pragma unroll 2
    for (int j = g; j < ncol; j += 4) {
        float4 al = *(const float4*)&s_alpha[j * 4];
        const float4 vv = *(const float4*)(vb + (size_t)s_off[j] * Cdim);
        A0.x = fmaf(al.x, vv.x, A0.x); A0.y = fmaf(al.x, vv.y, A0.y);
        A0.z = fmaf(al.x, vv.z, A0.z); A0.w = fmaf(al.x, vv.w, A0.w);
        A1.x = fmaf(al.y, vv.x, A1.x); A1.y = fmaf(al.y, vv.y, A1.y);
        A1.z = fmaf(al.y, vv.z, A1.z); A1.w = fmaf(al.y, vv.w, A1.w);
        A2.x = fmaf(al.z, vv.x, A2.x); A2.y = fmaf(al.z, vv.y, A2.y);
        A2.z = fmaf(al.z, vv.z, A2.z); A2.w = fmaf(al.z, vv.w, A2.w);
        A3.x = fmaf(al.w, vv.x, A3.x); A3.y = fmaf(al.w, vv.y, A3.y);
        A3.z = fmaf(al.w, vv.z, A3.z); A3.w = fmaf(al.w, vv.w, A3.w);
    }
    __syncthreads();
    float* sp = s_alpha;
    *(float4*)&sp[(0 * 4 + g) * 256 + c4] = A0;
    *(float4*)&sp[(1 * 4 + g) * 256 + c4] = A1;
    *(float4*)&sp[(2 * 4 + g) * 256 + c4] = A2;
    *(float4*)&sp[(3 * 4 + g) * 256 + c4] = A3;
    __syncthreads();

    float4 o;
    {
        float v0 = sp[(0*4+0)*256+tid] + sp[(0*4+1)*256+tid] + sp[(0*4+2)*256+tid] + sp[(0*4+3)*256+tid];
        float v1 = sp[(1*4+0)*256+tid] + sp[(1*4+1)*256+tid] + sp[(1*4+2)*256+tid] + sp[(1*4+3)*256+tid];
        float v2 = sp[(2*4+0)*256+tid] + sp[(2*4+1)*256+tid] + sp[(2*4+2)*256+tid] + sp[(2*4+3)*256+tid];
        float v3 = sp[(3*4+0)*256+tid] + sp[(3*4+1)*256+tid] + sp[(3*4+2)*256+tid] + sp[(3*4+3)*256+tid];
        o.x = v0 * s_inv[0]; o.y = v1 * s_inv[1]; o.z = v2 * s_inv[2]; o.w = v3 * s_inv[3];
    }
    *(float4*)(out + (((size_t)b * Cdim + tid) * Hlat + ho) * Wlon + wo0) = o;
}

// ---------------------------------------------------------------------------
extern "C" void kernel_launch(void* const* d_in, const int* in_sizes, int n_in,
                              void* d_out, int out_size) {
    const float* query = (const float*)d_in[0];
    const float* wq    = (const float*)d_in[1];
    const float* wk    = (const float*)d_in[2];
    const float* wv    = (const float*)d_in[3];
    const float* bq    = (const float*)d_in[4];
    const float* bk    = (const float*)d_in[5];
    const float* bv    = (const float*)d_in[6];
    const float* qw    = (const float*)d_in[7];
    const int*   rows  = (const int*)d_in[8];
    const int*   cols  = (const int*)d_in[9];
    int nnz = in_sizes[8];
    float* out = (float*)d_out;

    cudaFuncSetAttribute(qkv_mma_kernel,
                         cudaFuncAttributeMaxDynamicSharedMemorySize, GEMM_SMEM);

    zero_cnt_kernel<<<Hlat * Hlat / 256, 256>>>();
    count_kernel<<<(nnz + 255) / 256, 256>>>(rows, cols, nnz);
    arc_kernel<<<Hlat * Hlat / 256, 256>>>();
    convert_x_kernel<<<(Bdim * Cdim * HWsz / 4) / 256, 256>>>(query);
    convert_w_kernel<<<(3 * Cdim * Cdim / 4) / 256, 256>>>(wq, wk, wv);
    qkv_mma_kernel<<<dim3(HWsz / 128, 12, Bdim), 256, GEMM_SMEM>>>(bq, bk, bv);
    attn_kernel<<<dim3(Wlon / 4, Hlat, Bdim), 256>>>(qw, out);
}